// round 9
// baseline (speedup 1.0000x reference)
#include <cuda_runtime.h>

// Problem constants
#define B_DIM 8
#define C_DIM 1024
#define T_DIM 1024
#define H_DIM 8
#define DQK   128
#define DFC1  128

// ---------------------------------------------------------------------------
// Scratch (device globals: allocation-free rule)
// ---------------------------------------------------------------------------
__device__ float g_W1v[H_DIM * DFC1 * C_DIM];          // W1 @ Wv[h]      (4 MB)
__device__ float g_c1 [H_DIM * DFC1];                  // gamma*W1@bv + b1
__device__ float g_q  [B_DIM * H_DIM * DQK  * T_DIM];  // 32 MB
__device__ float g_k  [B_DIM * H_DIM * DQK  * T_DIM];  // 32 MB
__device__ float g_u  [B_DIM * H_DIM * DFC1 * T_DIM];  // 32 MB
__device__ float g_xw1[B_DIM * DFC1 * T_DIM];          // 4 MB

// ---------------------------------------------------------------------------
// Generic tiled SGEMM: C[z] (128 x 1024) = A (128 x 1024) * B[z] (1024 x 1024)
//   A offset = sA * (z % 8), B offset = sB * (z / bdiv), C offset = z*128*1024
//   optional bias per output row: bias + 128*(z%8)
// Block: 256 threads, tile 128x128, BK=16, 8x8 microtile.
// ---------------------------------------------------------------------------
__global__ __launch_bounds__(256) void sgemm128(
    const float* __restrict__ A, long sA,
    const float* __restrict__ B, long sB, int bdiv,
    float* __restrict__ Cmat,
    const float* __restrict__ bias)
{
    int z = blockIdx.z;
    const float* Ab = A + sA * (long)(z & 7);
    const float* Bb = B + sB * (long)(z / bdiv);
    float* Cb = Cmat + (long)z * (128 * 1024);
    const float* biasb = bias ? (bias + (z & 7) * 128) : nullptr;

    __shared__ float As[16 * 128];   // As[kk][m]
    __shared__ float Bs[16 * 128];   // Bs[kk][n]

    int tid = threadIdx.x;
    int tx = tid & 15, ty = tid >> 4;
    int colBase = blockIdx.x * 128;

    float acc[8][8];
#pragma unroll
    for (int i = 0; i < 8; i++)
#pragma unroll
        for (int j = 0; j < 8; j++) acc[i][j] = 0.f;

    for (int k0 = 0; k0 < 1024; k0 += 16) {
#pragma unroll
        for (int i = 0; i < 8; i++) {
            int idx = tid + i * 256;
            int m = idx >> 4, kk = idx & 15;
            As[kk * 128 + m] = Ab[m * 1024 + k0 + kk];
        }
#pragma unroll
        for (int i = 0; i < 8; i++) {
            int idx = tid + i * 256;
            int kk = idx >> 7, n = idx & 127;
            Bs[kk * 128 + n] = Bb[(k0 + kk) * 1024 + colBase + n];
        }
        __syncthreads();

#pragma unroll
        for (int kk = 0; kk < 16; kk++) {
            float4 a0 = *(const float4*)&As[kk * 128 + ty * 8];
            float4 a1 = *(const float4*)&As[kk * 128 + ty * 8 + 4];
            float4 b0 = *(const float4*)&Bs[kk * 128 + tx * 8];
            float4 b1 = *(const float4*)&Bs[kk * 128 + tx * 8 + 4];
            float ar[8] = {a0.x, a0.y, a0.z, a0.w, a1.x, a1.y, a1.z, a1.w};
            float br[8] = {b0.x, b0.y, b0.z, b0.w, b1.x, b1.y, b1.z, b1.w};
#pragma unroll
            for (int i = 0; i < 8; i++)
#pragma unroll
                for (int j = 0; j < 8; j++) acc[i][j] += ar[i] * br[j];
        }
        __syncthreads();
    }

#pragma unroll
    for (int i = 0; i < 8; i++) {
        int m = ty * 8 + i;
        float bb = biasb ? biasb[m] : 0.f;
        float4 v0 = make_float4(acc[i][0] + bb, acc[i][1] + bb, acc[i][2] + bb, acc[i][3] + bb);
        float4 v1 = make_float4(acc[i][4] + bb, acc[i][5] + bb, acc[i][6] + bb, acc[i][7] + bb);
        *(float4*)&Cb[m * 1024 + colBase + tx * 8]     = v0;
        *(float4*)&Cb[m * 1024 + colBase + tx * 8 + 4] = v1;
    }
}

// ---------------------------------------------------------------------------
// c1[h][f] = gamma[h] * sum_c W1[f][c]*bv[h][c] + b1[f]
// ---------------------------------------------------------------------------
__global__ void c1_kernel(const float* __restrict__ W1, const float* __restrict__ bv,
                          const float* __restrict__ b1, const float* __restrict__ gamma,
                          float* __restrict__ c1)
{
    int h = blockIdx.x, f = threadIdx.x;
    const float* bvh = bv + h * 1024;
    float s = 0.f;
    for (int c = 0; c < 1024; c++) s += W1[f * 1024 + c] * bvh[c];
    c1[h * 128 + f] = gamma[h] * s + b1[f];
}

// ---------------------------------------------------------------------------
// Fused flash attention + FC1 epilogue + FC2 + residual + output permute.
// Per block: one (b,h), 64 query rows. Online softmax over s-chunks of 64.
//   z[f,t] = sum_s u[f,s]*P[t,s]; y1 = relu(gamma*z + xw1 + c1);
//   y2 = relu(W2@y1 + b2); out[b, d*8+h, t] = y2[d] + x[b, d*8+h, t]
// Threads 256 as 16x16; GEMM1 micro 4x4 (q x s), GEMM2/3 micro 4x8 (q x f/d).
// ---------------------------------------------------------------------------
#define SMEM_FLOATS 29120
#define SMEM_BYTES  (SMEM_FLOATS * 4)

__global__ __launch_bounds__(256) void attn_fused(
    const float* __restrict__ qg, const float* __restrict__ kg,
    const float* __restrict__ ug, const float* __restrict__ xw1,
    const float* __restrict__ c1, const float* __restrict__ gamma,
    const float* __restrict__ W2, const float* __restrict__ b2,
    const float* __restrict__ x,  float* __restrict__ out)
{
    extern __shared__ float sm[];
    float* Qs   = sm;             // [128][64]      8192
    float* Ks   = sm + 8192;      // [128][64]      8192
    float* Us   = sm + 16384;     // [128][65]      8320
    float* Ss   = sm + 24704;     // [64][66]       4224
    float* m_sm = sm + 28928;     // [64]
    float* f_sm = m_sm + 64;      // [64]
    float* l_sm = f_sm + 64;      // [64]
    // epilogue aliases (overlap Qs/Ks/Us/Ss; l_sm region untouched)
    float* W2s = sm;              // [128][129]     16512  (W2s[f][d])
    float* y1s = sm + 16512;      // [64][132]      8448

    int tid = threadIdx.x;
    int tx = tid & 15, ty = tid >> 4;
    int qt = blockIdx.x;          // 0..15
    int h  = blockIdx.y;
    int b  = blockIdx.z;
    int bh = b * 8 + h;
    int t0 = qt * 64;

    const float* qb = qg + (long)bh * 128 * 1024;
    const float* kb = kg + (long)bh * 128 * 1024;
    const float* ub = ug + (long)bh * 128 * 1024;

    // Load Q tile: Qs[c][q]
    for (int i = tid; i < 128 * 64; i += 256) {
        int c = i >> 6, qq = i & 63;
        Qs[c * 64 + qq] = qb[c * 1024 + t0 + qq];
    }
    if (tid < 64) { m_sm[tid] = -1e30f; l_sm[tid] = 0.f; }
    __syncthreads();

    float acc2[4][8];
#pragma unroll
    for (int i = 0; i < 4; i++)
#pragma unroll
        for (int j = 0; j < 8; j++) acc2[i][j] = 0.f;

    for (int s0 = 0; s0 < 1024; s0 += 64) {
        // load K, U chunks
        for (int i = tid; i < 128 * 64; i += 256) {
            int c = i >> 6, ss = i & 63;
            Ks[c * 64 + ss] = kb[c * 1024 + s0 + ss];
            Us[c * 65 + ss] = ub[c * 1024 + s0 + ss];
        }
        __syncthreads();

        // GEMM1: S[q][s] = sum_c Q[c][q] K[c][s]
        float a1[16];
#pragma unroll
        for (int i = 0; i < 16; i++) a1[i] = 0.f;
#pragma unroll 8
        for (int c = 0; c < 128; c++) {
            float4 av = *(const float4*)&Qs[c * 64 + ty * 4];
            float4 kv = *(const float4*)&Ks[c * 64 + tx * 4];
            float ar[4] = {av.x, av.y, av.z, av.w};
            float br[4] = {kv.x, kv.y, kv.z, kv.w};
#pragma unroll
            for (int i = 0; i < 4; i++)
#pragma unroll
                for (int j = 0; j < 4; j++) a1[i * 4 + j] += ar[i] * br[j];
        }

        // chunk row-max (reduce across the 16 tx lanes; same ty = 16 contiguous lanes)
        float cm[4];
#pragma unroll
        for (int i = 0; i < 4; i++) {
            float m = a1[i * 4];
#pragma unroll
            for (int j = 1; j < 4; j++) m = fmaxf(m, a1[i * 4 + j]);
            cm[i] = m;
        }
#pragma unroll
        for (int o = 1; o < 16; o <<= 1)
#pragma unroll
            for (int i = 0; i < 4; i++)
                cm[i] = fmaxf(cm[i], __shfl_xor_sync(0xffffffffu, cm[i], o));

        if (tx == 0) {
#pragma unroll
            for (int i = 0; i < 4; i++) {
                int r = ty * 4 + i;
                float mo = m_sm[r];
                float mn = fmaxf(mo, cm[i]);
                m_sm[r] = mn;
                f_sm[r] = __expf(mo - mn);
            }
        }
        __syncthreads();

        // P = exp(S - m), row sums, rescale accumulators
        float ps[4];
#pragma unroll
        for (int i = 0; i < 4; i++) {
            int r = ty * 4 + i;
            float mn = m_sm[r];
            float s = 0.f;
#pragma unroll
            for (int j = 0; j < 4; j++) {
                float p = __expf(a1[i * 4 + j] - mn);
                Ss[r * 66 + tx * 4 + j] = p;
                s += p;
            }
            ps[i] = s;
        }
#pragma unroll
        for (int o = 1; o < 16; o <<= 1)
#pragma unroll
            for (int i = 0; i < 4; i++)
                ps[i] += __shfl_xor_sync(0xffffffffu, ps[i], o);

        float fc[4];
#pragma unroll
        for (int i = 0; i < 4; i++) fc[i] = f_sm[ty * 4 + i];
        if (tx == 0) {
#pragma unroll
            for (int i = 0; i < 4; i++) {
                int r = ty * 4 + i;
                l_sm[r] = l_sm[r] * fc[i] + ps[i];
            }
        }
#pragma unroll
        for (int i = 0; i < 4; i++)
#pragma unroll
            for (int j = 0; j < 8; j++) acc2[i][j] *= fc[i];
        __syncthreads();

        // GEMM2: acc2[q][f] += sum_s P[q][s] * U[f][s]
#pragma unroll 4
        for (int s = 0; s < 64; s++) {
            float ar[4], br[8];
#pragma unroll
            for (int i = 0; i < 4; i++) ar[i] = Ss[(ty * 4 + i) * 66 + s];
#pragma unroll
            for (int j = 0; j < 8; j++) br[j] = Us[(tx * 8 + j) * 65 + s];
#pragma unroll
            for (int i = 0; i < 4; i++)
#pragma unroll
                for (int j = 0; j < 8; j++) acc2[i][j] += ar[i] * br[j];
        }
        __syncthreads();
    }

    // ------------- epilogue: y1 = relu(gamma*z + xw1 + c1) -------------
    float linv[4];
#pragma unroll
    for (int i = 0; i < 4; i++) linv[i] = 1.f / l_sm[ty * 4 + i];
    float gam = __ldg(&gamma[h]);

#pragma unroll
    for (int i = 0; i < 4; i++) {
        int r = ty * 4 + i;
        int t = t0 + r;
#pragma unroll
        for (int j = 0; j < 8; j++) {
            int f = tx * 8 + j;
            float z = acc2[i][j] * linv[i];
            float y = gam * z + __ldg(&xw1[((long)b * 128 + f) * 1024 + t])
                              + __ldg(&c1[h * 128 + f]);
            y1s[r * 132 + f] = fmaxf(y, 0.f);
        }
    }
    // load W2 transposed into smem: W2s[f][d]
    for (int i2 = tid; i2 < 128 * 128; i2 += 256) {
        int d = i2 >> 7, f = i2 & 127;
        W2s[f * 129 + d] = W2[i2];
    }
    __syncthreads();

    // GEMM3: y2[q][d] = sum_f y1[q][f] * W2[d][f]
    float a3[4][8];
#pragma unroll
    for (int i = 0; i < 4; i++)
#pragma unroll
        for (int j = 0; j < 8; j++) a3[i][j] = 0.f;
#pragma unroll 4
    for (int f = 0; f < 128; f++) {
        float ar[4], br[8];
#pragma unroll
        for (int i = 0; i < 4; i++) ar[i] = y1s[(ty * 4 + i) * 132 + f];
#pragma unroll
        for (int j = 0; j < 8; j++) br[j] = W2s[f * 129 + tx * 8 + j];
#pragma unroll
        for (int i = 0; i < 4; i++)
#pragma unroll
            for (int j = 0; j < 8; j++) a3[i][j] += ar[i] * br[j];
    }

    // out[b, d*8+h, t] = relu(y2 + b2) + x[b, d*8+h, t]
#pragma unroll
    for (int j = 0; j < 8; j++) {
        int d = tx * 8 + j;
        int cch = d * 8 + h;
        long base = ((long)b * 1024 + cch) * 1024 + t0 + ty * 4;
        float bb = __ldg(&b2[d]);
        float4 xv = *(const float4*)&x[base];
        float4 ov;
        ov.x = fmaxf(a3[0][j] + bb, 0.f) + xv.x;
        ov.y = fmaxf(a3[1][j] + bb, 0.f) + xv.y;
        ov.z = fmaxf(a3[2][j] + bb, 0.f) + xv.z;
        ov.w = fmaxf(a3[3][j] + bb, 0.f) + xv.w;
        *(float4*)&out[base] = ov;
    }
}

// ---------------------------------------------------------------------------
extern "C" void kernel_launch(void* const* d_in, const int* in_sizes, int n_in,
                              void* d_out, int out_size)
{
    (void)in_sizes; (void)n_in; (void)out_size;
    const float* x     = (const float*)d_in[0];
    const float* Wq    = (const float*)d_in[1];
    const float* bq    = (const float*)d_in[2];
    const float* Wk    = (const float*)d_in[3];
    const float* bk    = (const float*)d_in[4];
    const float* Wv    = (const float*)d_in[5];
    const float* bv    = (const float*)d_in[6];
    const float* gamma = (const float*)d_in[7];
    const float* W1    = (const float*)d_in[8];
    const float* b1    = (const float*)d_in[9];
    const float* W2    = (const float*)d_in[10];
    const float* b2    = (const float*)d_in[11];
    float* out = (float*)d_out;

    float *pW1v, *pc1, *pq, *pk, *pu, *pxw1;
    cudaGetSymbolAddress((void**)&pW1v, g_W1v);
    cudaGetSymbolAddress((void**)&pc1,  g_c1);
    cudaGetSymbolAddress((void**)&pq,   g_q);
    cudaGetSymbolAddress((void**)&pk,   g_k);
    cudaGetSymbolAddress((void**)&pu,   g_u);
    cudaGetSymbolAddress((void**)&pxw1, g_xw1);

    cudaFuncSetAttribute(attn_fused, cudaFuncAttributeMaxDynamicSharedMemorySize, SMEM_BYTES);

    dim3 blk(256);
    // W1v[h] = W1 @ Wv[h]
    sgemm128<<<dim3(8, 1, 8),  blk>>>(W1, 0, Wv, (long)C_DIM * C_DIM, 1, pW1v, nullptr);
    // c1[h] = gamma*W1@bv + b1
    c1_kernel<<<8, 128>>>(W1, bv, b1, gamma, pc1);
    // q, k, u, xw1 projections
    sgemm128<<<dim3(8, 1, 64), blk>>>(Wq,   (long)DQK  * C_DIM, x, (long)C_DIM * T_DIM, 8, pq,   bq);
    sgemm128<<<dim3(8, 1, 64), blk>>>(Wk,   (long)DQK  * C_DIM, x, (long)C_DIM * T_DIM, 8, pk,   bk);
    sgemm128<<<dim3(8, 1, 64), blk>>>(pW1v, (long)DFC1 * C_DIM, x, (long)C_DIM * T_DIM, 8, pu,   nullptr);
    sgemm128<<<dim3(8, 1, 8),  blk>>>(W1, 0,                    x, (long)C_DIM * T_DIM, 1, pxw1, nullptr);
    // fused flash attention + MLP + residual
    attn_fused<<<dim3(16, 8, 8), blk, SMEM_BYTES>>>(pq, pk, pu, pxw1, pc1, gamma, W2, b2, x, out);
}

// round 11
// speedup vs baseline: 1.0093x; 1.0093x over previous
#include <cuda_runtime.h>

// Problem constants
#define B_DIM 8
#define C_DIM 1024
#define T_DIM 1024
#define H_DIM 8
#define DQK   128
#define DFC1  128

// ---------------------------------------------------------------------------
// Scratch (device globals: allocation-free rule)
// ---------------------------------------------------------------------------
__device__ float g_W1v[H_DIM * DFC1 * C_DIM];          // W1 @ Wv[h]      (4 MB)
__device__ float g_c1 [H_DIM * DFC1];                  // gamma*W1@bv + b1
__device__ float g_q  [B_DIM * H_DIM * DQK  * T_DIM];  // 32 MB
__device__ float g_k  [B_DIM * H_DIM * DQK  * T_DIM];  // 32 MB
__device__ float g_u  [B_DIM * H_DIM * DFC1 * T_DIM];  // 32 MB
__device__ float g_xw1[B_DIM * DFC1 * T_DIM];          // 4 MB

// ---------------------------------------------------------------------------
// Generic tiled SGEMM: C[z] (128 x 1024) = A (128 x 1024) * B[z] (1024 x 1024)
//   A offset = sA * (z % 8), B offset = sB * (z / bdiv), C offset = z*128*1024
//   optional bias per output row: bias + 128*(z%8)
// Block: 256 threads, tile 128x128, BK=16, 8x8 microtile.
// ---------------------------------------------------------------------------
__global__ __launch_bounds__(256) void sgemm128(
    const float* __restrict__ A, long sA,
    const float* __restrict__ B, long sB, int bdiv,
    float* __restrict__ Cmat,
    const float* __restrict__ bias)
{
    int z = blockIdx.z;
    const float* Ab = A + sA * (long)(z & 7);
    const float* Bb = B + sB * (long)(z / bdiv);
    float* Cb = Cmat + (long)z * (128 * 1024);
    const float* biasb = bias ? (bias + (z & 7) * 128) : nullptr;

    __shared__ float As[16 * 128];   // As[kk][m]
    __shared__ float Bs[16 * 128];   // Bs[kk][n]

    int tid = threadIdx.x;
    int tx = tid & 15, ty = tid >> 4;
    int colBase = blockIdx.x * 128;

    float acc[8][8];
#pragma unroll
    for (int i = 0; i < 8; i++)
#pragma unroll
        for (int j = 0; j < 8; j++) acc[i][j] = 0.f;

    for (int k0 = 0; k0 < 1024; k0 += 16) {
#pragma unroll
        for (int i = 0; i < 8; i++) {
            int idx = tid + i * 256;
            int m = idx >> 4, kk = idx & 15;
            As[kk * 128 + m] = Ab[m * 1024 + k0 + kk];
        }
#pragma unroll
        for (int i = 0; i < 8; i++) {
            int idx = tid + i * 256;
            int kk = idx >> 7, n = idx & 127;
            Bs[kk * 128 + n] = Bb[(k0 + kk) * 1024 + colBase + n];
        }
        __syncthreads();

#pragma unroll
        for (int kk = 0; kk < 16; kk++) {
            float4 a0 = *(const float4*)&As[kk * 128 + ty * 8];
            float4 a1 = *(const float4*)&As[kk * 128 + ty * 8 + 4];
            float4 b0 = *(const float4*)&Bs[kk * 128 + tx * 8];
            float4 b1 = *(const float4*)&Bs[kk * 128 + tx * 8 + 4];
            float ar[8] = {a0.x, a0.y, a0.z, a0.w, a1.x, a1.y, a1.z, a1.w};
            float br[8] = {b0.x, b0.y, b0.z, b0.w, b1.x, b1.y, b1.z, b1.w};
#pragma unroll
            for (int i = 0; i < 8; i++)
#pragma unroll
                for (int j = 0; j < 8; j++) acc[i][j] += ar[i] * br[j];
        }
        __syncthreads();
    }

#pragma unroll
    for (int i = 0; i < 8; i++) {
        int m = ty * 8 + i;
        float bb = biasb ? biasb[m] : 0.f;
        float4 v0 = make_float4(acc[i][0] + bb, acc[i][1] + bb, acc[i][2] + bb, acc[i][3] + bb);
        float4 v1 = make_float4(acc[i][4] + bb, acc[i][5] + bb, acc[i][6] + bb, acc[i][7] + bb);
        *(float4*)&Cb[m * 1024 + colBase + tx * 8]     = v0;
        *(float4*)&Cb[m * 1024 + colBase + tx * 8 + 4] = v1;
    }
}

// ---------------------------------------------------------------------------
// c1[h][f] = gamma[h] * sum_c W1[f][c]*bv[h][c] + b1[f]
// ---------------------------------------------------------------------------
__global__ void c1_kernel(const float* __restrict__ W1, const float* __restrict__ bv,
                          const float* __restrict__ b1, const float* __restrict__ gamma,
                          float* __restrict__ c1)
{
    int h = blockIdx.x, f = threadIdx.x;
    const float* bvh = bv + h * 1024;
    float s = 0.f;
    for (int c = 0; c < 1024; c++) s += W1[f * 1024 + c] * bvh[c];
    c1[h * 128 + f] = gamma[h] * s + b1[f];
}

// ---------------------------------------------------------------------------
// Fused flash attention + FC1 epilogue + FC2 + residual + output permute.
// Per block: one (b,h), 64 query rows. Online softmax over s-chunks of 64.
//   z[f,t] = sum_s u[f,s]*P[t,s]; y1 = relu(gamma*z + xw1 + c1);
//   y2 = relu(W2@y1 + b2); out[b, d*8+h, t] = y2[d] + x[b, d*8+h, t]
// Threads 256 as 16x16; GEMM1 micro 4x4 (q x s), GEMM2/3 micro 4x8 (q x f/d).
// ---------------------------------------------------------------------------
#define SMEM_FLOATS 29120
#define SMEM_BYTES  (SMEM_FLOATS * 4)

__global__ __launch_bounds__(256) void attn_fused(
    const float* __restrict__ qg, const float* __restrict__ kg,
    const float* __restrict__ ug, const float* __restrict__ xw1,
    const float* __restrict__ c1, const float* __restrict__ gamma,
    const float* __restrict__ W2, const float* __restrict__ b2,
    const float* __restrict__ x,  float* __restrict__ out)
{
    extern __shared__ float sm[];
    float* Qs   = sm;             // [128][64]      8192
    float* Ks   = sm + 8192;      // [128][64]      8192
    float* Us   = sm + 16384;     // [128][65]      8320
    float* Ss   = sm + 24704;     // [64][66]       4224
    float* m_sm = sm + 28928;     // [64]
    float* f_sm = m_sm + 64;      // [64]
    float* l_sm = f_sm + 64;      // [64]
    // epilogue aliases (overlap Qs/Ks/Us/Ss; l_sm region untouched)
    float* W2s = sm;              // [128][129]     16512  (W2s[f][d])
    float* y1s = sm + 16512;      // [64][132]      8448

    int tid = threadIdx.x;
    int tx = tid & 15, ty = tid >> 4;
    int qt = blockIdx.x;          // 0..15
    int h  = blockIdx.y;
    int b  = blockIdx.z;
    int bh = b * 8 + h;
    int t0 = qt * 64;

    const float* qb = qg + (long)bh * 128 * 1024;
    const float* kb = kg + (long)bh * 128 * 1024;
    const float* ub = ug + (long)bh * 128 * 1024;

    // Load Q tile: Qs[c][q]
    for (int i = tid; i < 128 * 64; i += 256) {
        int c = i >> 6, qq = i & 63;
        Qs[c * 64 + qq] = qb[c * 1024 + t0 + qq];
    }
    if (tid < 64) { m_sm[tid] = -1e30f; l_sm[tid] = 0.f; }
    __syncthreads();

    float acc2[4][8];
#pragma unroll
    for (int i = 0; i < 4; i++)
#pragma unroll
        for (int j = 0; j < 8; j++) acc2[i][j] = 0.f;

    for (int s0 = 0; s0 < 1024; s0 += 64) {
        // load K, U chunks
        for (int i = tid; i < 128 * 64; i += 256) {
            int c = i >> 6, ss = i & 63;
            Ks[c * 64 + ss] = kb[c * 1024 + s0 + ss];
            Us[c * 65 + ss] = ub[c * 1024 + s0 + ss];
        }
        __syncthreads();

        // GEMM1: S[q][s] = sum_c Q[c][q] K[c][s]
        float a1[16];
#pragma unroll
        for (int i = 0; i < 16; i++) a1[i] = 0.f;
#pragma unroll 8
        for (int c = 0; c < 128; c++) {
            float4 av = *(const float4*)&Qs[c * 64 + ty * 4];
            float4 kv = *(const float4*)&Ks[c * 64 + tx * 4];
            float ar[4] = {av.x, av.y, av.z, av.w};
            float br[4] = {kv.x, kv.y, kv.z, kv.w};
#pragma unroll
            for (int i = 0; i < 4; i++)
#pragma unroll
                for (int j = 0; j < 4; j++) a1[i * 4 + j] += ar[i] * br[j];
        }

        // chunk row-max (reduce across the 16 tx lanes; same ty = 16 contiguous lanes)
        float cm[4];
#pragma unroll
        for (int i = 0; i < 4; i++) {
            float m = a1[i * 4];
#pragma unroll
            for (int j = 1; j < 4; j++) m = fmaxf(m, a1[i * 4 + j]);
            cm[i] = m;
        }
#pragma unroll
        for (int o = 1; o < 16; o <<= 1)
#pragma unroll
            for (int i = 0; i < 4; i++)
                cm[i] = fmaxf(cm[i], __shfl_xor_sync(0xffffffffu, cm[i], o));

        if (tx == 0) {
#pragma unroll
            for (int i = 0; i < 4; i++) {
                int r = ty * 4 + i;
                float mo = m_sm[r];
                float mn = fmaxf(mo, cm[i]);
                m_sm[r] = mn;
                f_sm[r] = __expf(mo - mn);
            }
        }
        __syncthreads();

        // P = exp(S - m), row sums, rescale accumulators
        float ps[4];
#pragma unroll
        for (int i = 0; i < 4; i++) {
            int r = ty * 4 + i;
            float mn = m_sm[r];
            float s = 0.f;
#pragma unroll
            for (int j = 0; j < 4; j++) {
                float p = __expf(a1[i * 4 + j] - mn);
                Ss[r * 66 + tx * 4 + j] = p;
                s += p;
            }
            ps[i] = s;
        }
#pragma unroll
        for (int o = 1; o < 16; o <<= 1)
#pragma unroll
            for (int i = 0; i < 4; i++)
                ps[i] += __shfl_xor_sync(0xffffffffu, ps[i], o);

        float fc[4];
#pragma unroll
        for (int i = 0; i < 4; i++) fc[i] = f_sm[ty * 4 + i];
        if (tx == 0) {
#pragma unroll
            for (int i = 0; i < 4; i++) {
                int r = ty * 4 + i;
                l_sm[r] = l_sm[r] * fc[i] + ps[i];
            }
        }
#pragma unroll
        for (int i = 0; i < 4; i++)
#pragma unroll
            for (int j = 0; j < 8; j++) acc2[i][j] *= fc[i];
        __syncthreads();

        // GEMM2: acc2[q][f] += sum_s P[q][s] * U[f][s]
#pragma unroll 4
        for (int s = 0; s < 64; s++) {
            float ar[4], br[8];
#pragma unroll
            for (int i = 0; i < 4; i++) ar[i] = Ss[(ty * 4 + i) * 66 + s];
#pragma unroll
            for (int j = 0; j < 8; j++) br[j] = Us[(tx * 8 + j) * 65 + s];
#pragma unroll
            for (int i = 0; i < 4; i++)
#pragma unroll
                for (int j = 0; j < 8; j++) acc2[i][j] += ar[i] * br[j];
        }
        __syncthreads();
    }

    // ------------- epilogue: y1 = relu(gamma*z + xw1 + c1) -------------
    float linv[4];
#pragma unroll
    for (int i = 0; i < 4; i++) linv[i] = 1.f / l_sm[ty * 4 + i];
    float gam = __ldg(&gamma[h]);

#pragma unroll
    for (int i = 0; i < 4; i++) {
        int r = ty * 4 + i;
        int t = t0 + r;
#pragma unroll
        for (int j = 0; j < 8; j++) {
            int f = tx * 8 + j;
            float z = acc2[i][j] * linv[i];
            float y = gam * z + __ldg(&xw1[((long)b * 128 + f) * 1024 + t])
                              + __ldg(&c1[h * 128 + f]);
            y1s[r * 132 + f] = fmaxf(y, 0.f);
        }
    }
    // load W2 transposed into smem: W2s[f][d]
    for (int i2 = tid; i2 < 128 * 128; i2 += 256) {
        int d = i2 >> 7, f = i2 & 127;
        W2s[f * 129 + d] = W2[i2];
    }
    __syncthreads();

    // GEMM3: y2[q][d] = sum_f y1[q][f] * W2[d][f]
    float a3[4][8];
#pragma unroll
    for (int i = 0; i < 4; i++)
#pragma unroll
        for (int j = 0; j < 8; j++) a3[i][j] = 0.f;
#pragma unroll 4
    for (int f = 0; f < 128; f++) {
        float ar[4], br[8];
#pragma unroll
        for (int i = 0; i < 4; i++) ar[i] = y1s[(ty * 4 + i) * 132 + f];
#pragma unroll
        for (int j = 0; j < 8; j++) br[j] = W2s[f * 129 + tx * 8 + j];
#pragma unroll
        for (int i = 0; i < 4; i++)
#pragma unroll
            for (int j = 0; j < 8; j++) a3[i][j] += ar[i] * br[j];
    }

    // out[b, d*8+h, t] = relu(y2 + b2) + x[b, d*8+h, t]
#pragma unroll
    for (int j = 0; j < 8; j++) {
        int d = tx * 8 + j;
        int cch = d * 8 + h;
        long base = ((long)b * 1024 + cch) * 1024 + t0 + ty * 4;
        float bb = __ldg(&b2[d]);
        float4 xv = *(const float4*)&x[base];
        float4 ov;
        ov.x = fmaxf(a3[0][j] + bb, 0.f) + xv.x;
        ov.y = fmaxf(a3[1][j] + bb, 0.f) + xv.y;
        ov.z = fmaxf(a3[2][j] + bb, 0.f) + xv.z;
        ov.w = fmaxf(a3[3][j] + bb, 0.f) + xv.w;
        *(float4*)&out[base] = ov;
    }
}

// ---------------------------------------------------------------------------
extern "C" void kernel_launch(void* const* d_in, const int* in_sizes, int n_in,
                              void* d_out, int out_size)
{
    (void)in_sizes; (void)n_in; (void)out_size;
    const float* x     = (const float*)d_in[0];
    const float* Wq    = (const float*)d_in[1];
    const float* bq    = (const float*)d_in[2];
    const float* Wk    = (const float*)d_in[3];
    const float* bk    = (const float*)d_in[4];
    const float* Wv    = (const float*)d_in[5];
    const float* bv    = (const float*)d_in[6];
    const float* gamma = (const float*)d_in[7];
    const float* W1    = (const float*)d_in[8];
    const float* b1    = (const float*)d_in[9];
    const float* W2    = (const float*)d_in[10];
    const float* b2    = (const float*)d_in[11];
    float* out = (float*)d_out;

    float *pW1v, *pc1, *pq, *pk, *pu, *pxw1;
    cudaGetSymbolAddress((void**)&pW1v, g_W1v);
    cudaGetSymbolAddress((void**)&pc1,  g_c1);
    cudaGetSymbolAddress((void**)&pq,   g_q);
    cudaGetSymbolAddress((void**)&pk,   g_k);
    cudaGetSymbolAddress((void**)&pu,   g_u);
    cudaGetSymbolAddress((void**)&pxw1, g_xw1);

    cudaFuncSetAttribute(attn_fused, cudaFuncAttributeMaxDynamicSharedMemorySize, SMEM_BYTES);

    dim3 blk(256);
    // W1v[h] = W1 @ Wv[h]
    sgemm128<<<dim3(8, 1, 8),  blk>>>(W1, 0, Wv, (long)C_DIM * C_DIM, 1, pW1v, nullptr);
    // c1[h] = gamma*W1@bv + b1
    c1_kernel<<<8, 128>>>(W1, bv, b1, gamma, pc1);
    // q, k, u, xw1 projections
    sgemm128<<<dim3(8, 1, 64), blk>>>(Wq,   (long)DQK  * C_DIM, x, (long)C_DIM * T_DIM, 8, pq,   bq);
    sgemm128<<<dim3(8, 1, 64), blk>>>(Wk,   (long)DQK  * C_DIM, x, (long)C_DIM * T_DIM, 8, pk,   bk);
    sgemm128<<<dim3(8, 1, 64), blk>>>(pW1v, (long)DFC1 * C_DIM, x, (long)C_DIM * T_DIM, 8, pu,   nullptr);
    sgemm128<<<dim3(8, 1, 8),  blk>>>(W1, 0,                    x, (long)C_DIM * T_DIM, 1, pxw1, nullptr);
    // fused flash attention + MLP + residual
    attn_fused<<<dim3(16, 8, 8), blk, SMEM_BYTES>>>(pq, pk, pu, pxw1, pc1, gamma, W2, b2, x, out);
}